// round 1
// baseline (speedup 1.0000x reference)
#include <cuda_runtime.h>
#include <cstdint>

#define B_   64
#define T_   1024
#define H_   512
#define I_   64
#define O_   8
#define ALPHA 0.2f
#define NSTD  0.05f

#define NBT  8                 // batch tiles
#define NCT  16                // column tiles
#define GRID (NBT*NCT)         // 128 CTAs (single wave on 148 SMs)
#define THREADS 128
#define BPC  (B_/NBT)          // 8 batches per CTA
#define CPC  (H_/NCT)          // 32 cols per CTA
#define KTOT (H_+I_)           // 576 unified reduction dim (wrec + wi)
#define KSUBS 8
#define KPER (H_/KSUBS)        // 64 wrec-k per thread
#define IPER (I_/KSUBS)        // 8 wi-k per thread
#define WREGS (KPER+IPER)      // 72 packed weight regs per thread

// persistent device state (allowed: __device__ globals, no allocation)
__device__ float g_h[2][B_][H_];
__device__ unsigned long long g_bar = 0ULL;   // monotonic barrier ticket

// ---- packed f32x2 helpers (sm_100+) ----
__device__ __forceinline__ unsigned long long pk2(float lo, float hi) {
    unsigned long long v;
    asm("mov.b64 %0, {%1,%2};" : "=l"(v) : "f"(lo), "f"(hi));
    return v;
}
__device__ __forceinline__ void ffma2(unsigned long long& d,
                                      unsigned long long a,
                                      unsigned long long b) {
    asm("fma.rn.f32x2 %0, %1, %2, %0;" : "+l"(d) : "l"(a), "l"(b));
}
__device__ __forceinline__ unsigned long long fadd2(unsigned long long a,
                                                    unsigned long long b) {
    unsigned long long d;
    asm("add.rn.f32x2 %0, %1, %2;" : "=l"(d) : "l"(a), "l"(b));
    return d;
}
__device__ __forceinline__ float lo32(unsigned long long v) {
    return __uint_as_float((unsigned)(v & 0xffffffffu));
}
__device__ __forceinline__ float hi32(unsigned long long v) {
    return __uint_as_float((unsigned)(v >> 32));
}

// grid-wide barrier: monotonic ticket counter; all GRID CTAs are co-resident
__device__ __forceinline__ void grid_barrier() {
    __syncthreads();
    if (threadIdx.x == 0) {
        __threadfence();
        unsigned long long t = atomicAdd(&g_bar, 1ULL);
        unsigned long long target = t - (t % (unsigned long long)GRID)
                                      + (unsigned long long)GRID;
        unsigned long long v;
        do {
            asm volatile("ld.volatile.global.u64 %0, [%1];"
                         : "=l"(v) : "l"(&g_bar));
        } while (v < target);
        __threadfence();
    }
    __syncthreads();
}

extern "C" __global__ void __launch_bounds__(THREADS, 1)
rnn_main(const float* __restrict__ input, const float* __restrict__ noise,
         const float* __restrict__ wi, const float* __restrict__ si,
         const float* __restrict__ wrec, const float* __restrict__ bias,
         const float* __restrict__ wi_mask, const float* __restrict__ wrec_mask,
         const float* __restrict__ h0, float* __restrict__ traj)
{
    __shared__ __align__(16) unsigned long long s_op[BPC * KTOT];       // 36 KB: dup'd operands
    __shared__ __align__(16) unsigned long long s_red[BPC][16][KSUBS];  // 8 KB: k-split partials

    const int tid   = threadIdx.x;
    const int bt    = blockIdx.x / NCT;
    const int ct    = blockIdx.x % NCT;
    const int B0    = bt * BPC;
    const int C0    = ct * CPC;
    const int cpair = tid & 15;          // column pair within tile
    const int ksub  = tid >> 4;          // k-slice [0,8)
    const int c0    = C0 + cpair * 2;    // global first column
    const int kbase = ksub * KPER;
    const int ibase = ksub * IPER;

    // -------- preload effective weights into registers (constant over t) ----
    unsigned long long w2[WREGS];
#pragma unroll
    for (int j = 0; j < KPER; j++) {
        int k = kbase + j;
        float2 wv = *(const float2*)(wrec      + (size_t)k * H_ + c0);
        float2 mv = *(const float2*)(wrec_mask + (size_t)k * H_ + c0);
        w2[j] = pk2(fabsf(wv.x) * mv.x, fabsf(wv.y) * mv.y);
    }
#pragma unroll
    for (int j = 0; j < IPER; j++) {
        int i = ibase + j;
        float sc = si[i];
        float2 wv = *(const float2*)(wi      + (size_t)i * H_ + c0);
        float2 mv = *(const float2*)(wi_mask + (size_t)i * H_ + c0);
        w2[KPER + j] = pk2(wv.x * sc * mv.x, wv.y * sc * mv.y);
    }

    // finalize-role indices (same numeric mapping: fb==ksub, col pair==cpair)
    const int fb = tid >> 4;                 // batch within tile for finalize
    const float2 fbias = *(const float2*)(bias + c0);

    // -------- init: h(0) = h0 broadcast; trajectories[:,0,:] = h0 ----------
    {
        float2 h0v = *(const float2*)(h0 + c0);
        *(float2*)&g_h[0][B0 + fb][c0] = h0v;
        *(float2*)&traj[((size_t)(B0 + fb) * (T_ + 1)) * H_ + c0] = h0v;
    }
    __threadfence();
    grid_barrier();

    int p = 0;
    for (int t = 0; t < T_; t++) {
        // ---- stage: dup(relu(h_prev)) for k<H, dup(x_t) for k>=H ----------
        for (int s = tid; s < BPC * (KTOT / 2); s += THREADS) {
            int b  = s / (KTOT / 2);
            int kk = (s - b * (KTOT / 2)) * 2;
            float2 v;
            if (kk < H_) {
                v = *(const float2*)&g_h[p][B0 + b][kk];
                v.x = fmaxf(v.x, 0.f);
                v.y = fmaxf(v.y, 0.f);
            } else {
                int ii = kk - H_;
                v = *(const float2*)(input + ((size_t)(B0 + b) * T_ + t) * I_ + ii);
            }
            ulonglong2 d;
            d.x = pk2(v.x, v.x);
            d.y = pk2(v.y, v.y);
            *(ulonglong2*)&s_op[b * KTOT + kk] = d;
        }
        __syncthreads();

        // prefetch finalize operands early to hide latency behind the matmul
        float2 nz   = *(const float2*)(noise + ((size_t)(B0 + fb) * T_ + t) * H_ + c0);
        float2 hold = *(const float2*)&g_h[p][B0 + fb][c0];

        // ---- unified packed matmul: acc[b] += dup(op) * w2 over 576 k -----
        unsigned long long acc[BPC];
#pragma unroll
        for (int b = 0; b < BPC; b++) acc[b] = 0ULL;

#pragma unroll
        for (int j2 = 0; j2 < KPER / 2; j2++) {
#pragma unroll
            for (int b = 0; b < BPC; b++) {
                ulonglong2 v = *(const ulonglong2*)&s_op[b * KTOT + kbase + j2 * 2];
                ffma2(acc[b], v.x, w2[2 * j2]);
                ffma2(acc[b], v.y, w2[2 * j2 + 1]);
            }
        }
#pragma unroll
        for (int j2 = 0; j2 < IPER / 2; j2++) {
#pragma unroll
            for (int b = 0; b < BPC; b++) {
                ulonglong2 v = *(const ulonglong2*)&s_op[b * KTOT + H_ + ibase + j2 * 2];
                ffma2(acc[b], v.x, w2[KPER + 2 * j2]);
                ffma2(acc[b], v.y, w2[KPER + 2 * j2 + 1]);
            }
        }

        // ---- k-split reduction across the 8 ksub threads ------------------
#pragma unroll
        for (int b = 0; b < BPC; b++)
            s_red[b][cpair][ksub] = acc[b];
        __syncthreads();

        ulonglong2 q0 = *(const ulonglong2*)&s_red[fb][cpair][0];
        ulonglong2 q1 = *(const ulonglong2*)&s_red[fb][cpair][2];
        ulonglong2 q2 = *(const ulonglong2*)&s_red[fb][cpair][4];
        ulonglong2 q3 = *(const ulonglong2*)&s_red[fb][cpair][6];
        unsigned long long sa = fadd2(fadd2(q0.x, q0.y), fadd2(q1.x, q1.y));
        unsigned long long sb = fadd2(fadd2(q2.x, q2.y), fadd2(q3.x, q3.y));
        unsigned long long ss = fadd2(sa, sb);
        float accx = lo32(ss);
        float accy = hi32(ss);

        // ---- h update + outputs -------------------------------------------
        float hx = hold.x + NSTD * nz.x + ALPHA * (-hold.x + accx + fbias.x);
        float hy = hold.y + NSTD * nz.y + ALPHA * (-hold.y + accy + fbias.y);
        float2 hn = make_float2(hx, hy);
        *(float2*)&g_h[1 - p][B0 + fb][c0] = hn;
        *(float2*)&traj[((size_t)(B0 + fb) * (T_ + 1) + (t + 1)) * H_ + c0] = hn;

        __threadfence();
        grid_barrier();
        p ^= 1;
    }
}

// output pass: out[b,t,o] = relu(traj[b,t+1,:]) @ wo_eff
extern "C" __global__ void __launch_bounds__(256)
rnn_out(const float* __restrict__ traj, const float* __restrict__ wo,
        const float* __restrict__ so, const float* __restrict__ wo_mask,
        float* __restrict__ out)
{
    __shared__ float s_wo[O_][H_];   // transposed for conflict-free LDS
    const int tid = threadIdx.x;
    for (int i = tid; i < H_ * O_; i += 256) {
        int c = i / O_, o = i % O_;
        s_wo[o][c] = wo[i] * so[o] * wo_mask[i];
    }
    __syncthreads();

    const int warp = tid >> 5, lane = tid & 31;
    const size_t row = (size_t)blockIdx.x * 8 + warp;   // b*T + t
    const int b = (int)(row >> 10);
    const int t = (int)(row & 1023);
    const float* tp = traj + ((size_t)b * (T_ + 1) + t + 1) * H_;

    float acc[O_];
#pragma unroll
    for (int o = 0; o < O_; o++) acc[o] = 0.f;

    for (int cc = 0; cc < H_; cc += 32) {
        float r = fmaxf(tp[cc + lane], 0.f);
#pragma unroll
        for (int o = 0; o < O_; o++) acc[o] += r * s_wo[o][cc + lane];
    }
#pragma unroll
    for (int off = 16; off; off >>= 1)
#pragma unroll
        for (int o = 0; o < O_; o++)
            acc[o] += __shfl_down_sync(0xffffffffu, acc[o], off);
    if (lane == 0) {
#pragma unroll
        for (int o = 0; o < O_; o++) out[row * O_ + o] = acc[o];
    }
}

extern "C" void kernel_launch(void* const* d_in, const int* in_sizes, int n_in,
                              void* d_out, int out_size)
{
    (void)in_sizes; (void)n_in; (void)out_size;
    const float* input = (const float*)d_in[0];
    const float* noise = (const float*)d_in[1];
    const float* wi    = (const float*)d_in[2];
    const float* si    = (const float*)d_in[3];
    const float* wrec  = (const float*)d_in[4];
    const float* bias  = (const float*)d_in[5];
    const float* wo    = (const float*)d_in[6];
    const float* so    = (const float*)d_in[7];
    const float* wim   = (const float*)d_in[8];
    const float* wrm   = (const float*)d_in[9];
    const float* wom   = (const float*)d_in[10];
    const float* h0    = (const float*)d_in[11];

    float* out  = (float*)d_out;
    float* traj = out + (size_t)B_ * T_ * O_;   // [B, T+1, H] after [B, T, O]

    rnn_main<<<GRID, THREADS>>>(input, noise, wi, si, wrec, bias,
                                wim, wrm, h0, traj);
    rnn_out<<<(B_ * T_) / 8, 256>>>(traj, wo, so, wom, out);
}

// round 2
// speedup vs baseline: 1.3327x; 1.3327x over previous
#include <cuda_runtime.h>
#include <cstdint>

#define B_   64
#define T_   1024
#define H_   512
#define I_   64
#define O_   8
#define ALPHA 0.2f
#define NSTD  0.05f

#define CL    8                 // cluster size (column tiles per batch group)
#define NBG   16                // batch groups (clusters)
#define GRID  (CL*NBG)          // 128 CTAs
#define TPB   256
#define NB    4                 // batches per cluster/CTA
#define NC    64                // columns per CTA
#define KTOT  (H_+I_)           // 576
#define KS    8                 // k-slices
#define NPAIR 36                // k-pairs per thread (64 wrec + 8 wi)/2

// ---- packed f32x2 helpers (sm_100+) ----
__device__ __forceinline__ unsigned long long pk2(float lo, float hi) {
    unsigned long long v;
    asm("mov.b64 %0, {%1,%2};" : "=l"(v) : "f"(lo), "f"(hi));
    return v;
}
__device__ __forceinline__ void ffma2(unsigned long long& d,
                                      unsigned long long a,
                                      unsigned long long b) {
    asm("fma.rn.f32x2 %0, %1, %2, %0;" : "+l"(d) : "l"(a), "l"(b));
}
__device__ __forceinline__ unsigned long long fadd2(unsigned long long a,
                                                    unsigned long long b) {
    unsigned long long d;
    asm("add.rn.f32x2 %0, %1, %2;" : "=l"(d) : "l"(a), "l"(b));
    return d;
}
__device__ __forceinline__ float lo32(unsigned long long v) {
    return __uint_as_float((unsigned)(v & 0xffffffffu));
}
__device__ __forceinline__ float hi32(unsigned long long v) {
    return __uint_as_float((unsigned)(v >> 32));
}
__device__ __forceinline__ uint32_t smem_u32(const void* p) {
    uint32_t a;
    asm("{ .reg .u64 t; cvta.to.shared.u64 t, %1; cvt.u32.u64 %0, t; }"
        : "=r"(a) : "l"(p));
    return a;
}
// remote (cluster) shared-memory scalar store
__device__ __forceinline__ void dsmem_st(uint32_t laddr, uint32_t rank, float v) {
    asm volatile(
        "{ .reg .u32 ra; mapa.shared::cluster.u32 ra, %0, %1;"
        "  st.shared::cluster.f32 [ra], %2; }"
        :: "r"(laddr), "r"(rank), "f"(v) : "memory");
}
__device__ __forceinline__ void cluster_sync() {
    asm volatile("barrier.cluster.arrive.aligned;" ::: "memory");
    asm volatile("barrier.cluster.wait.aligned;" ::: "memory");
}

extern "C" __global__ void __launch_bounds__(TPB, 1) __cluster_dims__(CL, 1, 1)
rnn_main(const float* __restrict__ input, const float* __restrict__ noise,
         const float* __restrict__ wi, const float* __restrict__ si,
         const float* __restrict__ wrec, const float* __restrict__ bias,
         const float* __restrict__ wi_mask, const float* __restrict__ wrec_mask,
         const float* __restrict__ h0, float* __restrict__ traj)
{
    // operand buffer: relu(h) for k<512, x_t for k>=512; double buffered
    __shared__ __align__(16) float s_op[2][NB][KTOT];          // 18 KB
    __shared__ __align__(16) unsigned long long s_red[NB][KS][NC + 2]; // 16.9 KB

    const int tid  = threadIdx.x;
    const int rank = blockIdx.x % CL;     // column tile
    const int bg   = blockIdx.x / CL;     // batch group
    const int C0   = rank * NC;           // first global column of this CTA
    const int B0   = bg * NB;             // first batch of this cluster

    // compute-role: 32 column-threads (2 cols each) x 8 k-slices
    const int ct   = tid & 31;            // column-thread
    const int ksub = tid >> 5;            // k-slice
    const int col0 = C0 + ct * 2;         // first of my 2 global columns
    const int kb   = ksub * (H_ / KS);    // 64 wrec k's start
    const int ib   = ksub * (I_ / KS);    // 8 wi k's start (within x region)

    // finalize-role: 256 threads <-> (batch, col) pairs
    const int fb = tid >> 6;              // batch within group [0,4)
    const int fc = tid & 63;              // column within tile [0,64)
    const int gb = B0 + fb;               // global batch
    const int gc = C0 + fc;               // global column

    // -------- preload effective weights, packed by (k,k+1) per column ------
    // w2[p*2 + c] covers pair p (k = kb+2p / wi for p>=32) for column col0+c
    unsigned long long w2[NPAIR * 2];
#pragma unroll
    for (int p = 0; p < 32; p++) {
        int k0 = kb + 2 * p;
#pragma unroll
        for (int c = 0; c < 2; c++) {
            int cc = col0 + c;
            float a = fabsf(wrec[(size_t)k0 * H_ + cc]) * wrec_mask[(size_t)k0 * H_ + cc];
            float b = fabsf(wrec[(size_t)(k0 + 1) * H_ + cc]) * wrec_mask[(size_t)(k0 + 1) * H_ + cc];
            w2[p * 2 + c] = pk2(a, b);
        }
    }
#pragma unroll
    for (int p = 32; p < NPAIR; p++) {
        int i0 = ib + 2 * (p - 32);
#pragma unroll
        for (int c = 0; c < 2; c++) {
            int cc = col0 + c;
            float a = wi[(size_t)i0 * H_ + cc] * si[i0] * wi_mask[(size_t)i0 * H_ + cc];
            float b = wi[(size_t)(i0 + 1) * H_ + cc] * si[i0 + 1] * wi_mask[(size_t)(i0 + 1) * H_ + cc];
            w2[p * 2 + c] = pk2(a, b);
        }
    }

    const float fbias = bias[gc];
    const uint32_t s_op_u32 = smem_u32(&s_op[0][0][0]);

    // -------- init: stage relu(h0) + x_0 locally; h_prev in registers ------
    float h_prev = h0[gc];
    traj[((size_t)gb * (T_ + 1)) * H_ + gc] = h_prev;
#pragma unroll
    for (int q = 0; q < 8; q++) {
        int idx = tid * 8 + q;            // [0, 2048): b = idx>>9, k = idx&511
        int b = idx >> 9, k = idx & 511;
        s_op[0][b][k] = fmaxf(h0[k], 0.f);
    }
    if (tid < 128) {
        int xb = tid >> 5, xi = (tid & 31) * 2;
        float2 xv = *(const float2*)(input + ((size_t)(B0 + xb) * T_) * I_ + xi);
        *(float2*)&s_op[0][xb][H_ + xi] = xv;
    }
    __syncthreads();

    int p = 0;
    for (int t = 0; t < T_; t++) {
        // ---- early loads (consumed at step end; hidden behind matmul) -----
        float nz = noise[((size_t)gb * T_ + t) * H_ + gc];
        float2 xnext = make_float2(0.f, 0.f);
        if (tid < 128 && t + 1 < T_) {
            int xb = tid >> 5, xi = (tid & 31) * 2;
            xnext = *(const float2*)(input + ((size_t)(B0 + xb) * T_ + t + 1) * I_ + xi);
        }

        // ---- matmul: acc[b][c] over 72 k (packed pairs) -------------------
        unsigned long long acc[NB][2];
#pragma unroll
        for (int b = 0; b < NB; b++) { acc[b][0] = 0ULL; acc[b][1] = 0ULL; }

#pragma unroll
        for (int j2 = 0; j2 < 18; j2++) {
            const int off = (j2 < 16) ? (kb + 4 * j2) : (H_ + ib + 4 * (j2 - 16));
#pragma unroll
            for (int b = 0; b < NB; b++) {
                ulonglong2 v = *(const ulonglong2*)&s_op[p][b][off];
                ffma2(acc[b][0], v.x, w2[(2 * j2) * 2 + 0]);
                ffma2(acc[b][1], v.x, w2[(2 * j2) * 2 + 1]);
                ffma2(acc[b][0], v.y, w2[(2 * j2 + 1) * 2 + 0]);
                ffma2(acc[b][1], v.y, w2[(2 * j2 + 1) * 2 + 1]);
            }
        }

        // ---- k-slice reduction through smem -------------------------------
#pragma unroll
        for (int b = 0; b < NB; b++) {
            s_red[b][ksub][ct * 2 + 0] = acc[b][0];
            s_red[b][ksub][ct * 2 + 1] = acc[b][1];
        }
        __syncthreads();

        unsigned long long r0 = s_red[fb][0][fc], r1 = s_red[fb][1][fc];
        unsigned long long r2 = s_red[fb][2][fc], r3 = s_red[fb][3][fc];
        unsigned long long r4 = s_red[fb][4][fc], r5 = s_red[fb][5][fc];
        unsigned long long r6 = s_red[fb][6][fc], r7 = s_red[fb][7][fc];
        unsigned long long s01 = fadd2(fadd2(r0, r1), fadd2(r2, r3));
        unsigned long long s23 = fadd2(fadd2(r4, r5), fadd2(r6, r7));
        unsigned long long ss  = fadd2(s01, s23);
        float sum = lo32(ss) + hi32(ss);

        // ---- h update + trajectory + relu broadcast to cluster ------------
        float h_new = h_prev + NSTD * nz + ALPHA * (-h_prev + sum + fbias);
        traj[((size_t)gb * (T_ + 1) + (t + 1)) * H_ + gc] = h_new;
        h_prev = h_new;
        float rv = fmaxf(h_new, 0.f);

        const int pn = p ^ 1;
        uint32_t la = s_op_u32 + (uint32_t)(((pn * NB + fb) * KTOT + gc) * 4);
#pragma unroll
        for (int r = 0; r < CL; r++) dsmem_st(la, (uint32_t)r, rv);

        // stage x_{t+1} into the next buffer (local smem)
        if (tid < 128) {
            int xb = tid >> 5, xi = (tid & 31) * 2;
            *(float2*)&s_op[pn][xb][H_ + xi] = xnext;
        }

        cluster_sync();
        p = pn;
    }
}

// output pass: out[b,t,o] = relu(traj[b,t+1,:]) @ wo_eff
extern "C" __global__ void __launch_bounds__(256)
rnn_out(const float* __restrict__ traj, const float* __restrict__ wo,
        const float* __restrict__ so, const float* __restrict__ wo_mask,
        float* __restrict__ out)
{
    __shared__ float s_wo[O_][H_];
    const int tid = threadIdx.x;
    for (int i = tid; i < H_ * O_; i += 256) {
        int c = i / O_, o = i % O_;
        s_wo[o][c] = wo[i] * so[o] * wo_mask[i];
    }
    __syncthreads();

    const int warp = tid >> 5, lane = tid & 31;
    const size_t row = (size_t)blockIdx.x * 8 + warp;   // b*T + t
    const int b = (int)(row >> 10);
    const int t = (int)(row & 1023);
    const float* tp = traj + ((size_t)b * (T_ + 1) + t + 1) * H_;

    float acc[O_];
#pragma unroll
    for (int o = 0; o < O_; o++) acc[o] = 0.f;

    for (int cc = 0; cc < H_; cc += 32) {
        float r = fmaxf(tp[cc + lane], 0.f);
#pragma unroll
        for (int o = 0; o < O_; o++) acc[o] += r * s_wo[o][cc + lane];
    }
#pragma unroll
    for (int off = 16; off; off >>= 1)
#pragma unroll
        for (int o = 0; o < O_; o++)
            acc[o] += __shfl_down_sync(0xffffffffu, acc[o], off);
    if (lane == 0) {
#pragma unroll
        for (int o = 0; o < O_; o++) out[row * O_ + o] = acc[o];
    }
}

extern "C" void kernel_launch(void* const* d_in, const int* in_sizes, int n_in,
                              void* d_out, int out_size)
{
    (void)in_sizes; (void)n_in; (void)out_size;
    const float* input = (const float*)d_in[0];
    const float* noise = (const float*)d_in[1];
    const float* wi    = (const float*)d_in[2];
    const float* si    = (const float*)d_in[3];
    const float* wrec  = (const float*)d_in[4];
    const float* bias  = (const float*)d_in[5];
    const float* wo    = (const float*)d_in[6];
    const float* so    = (const float*)d_in[7];
    const float* wim   = (const float*)d_in[8];
    const float* wrm   = (const float*)d_in[9];
    const float* wom   = (const float*)d_in[10];
    const float* h0    = (const float*)d_in[11];

    float* out  = (float*)d_out;
    float* traj = out + (size_t)B_ * T_ * O_;   // [B, T+1, H] after [B, T, O]

    rnn_main<<<GRID, TPB>>>(input, noise, wi, si, wrec, bias,
                            wim, wrm, h0, traj);
    rnn_out<<<(B_ * T_) / 8, 256>>>(traj, wo, so, wom, out);
}